// round 1
// baseline (speedup 1.0000x reference)
#include <cuda_runtime.h>
#include <math.h>
#include <stdint.h>

// ---------------- problem constants ----------------
#define NL    6
#define DMODEL 768
#define NH    12
#define DFF_  3072
#define BB    8
#define TLEN_ 512
#define SLEN_ 512
#define DH_   64
#define BT_   (BB*TLEN_)   // 4096 target tokens
#define BS_   (BB*SLEN_)   // 4096 source tokens

// ---------------- scratch (device globals: allocation-free) ----------------
__device__ float g_res [BT_*DMODEL];
__device__ float g_res2[BT_*DMODEL];
__device__ float g_lnb [BT_*DMODEL];
__device__ float g_qkv [BT_*3*DMODEL];
__device__ float g_kv  [BS_*2*DMODEL];
__device__ float g_ctx [BT_*DMODEL];
__device__ float g_ff  [BT_*DFF_];

// ---------------- embedding + positional encoding ----------------
__global__ void embed_kernel(const int* __restrict__ tgt,
                             const float* __restrict__ emb,
                             float* __restrict__ out)
{
    int row = blockIdx.x;              // b*T + t
    int t   = row & (TLEN_ - 1);
    int tok = tgt[row];
    const float* e = emb + (size_t)tok * DMODEL;
    const float c = (float)(-9.210340371976184 / (double)DMODEL);  // -ln(10000)/D
    for (int d = threadIdx.x; d < DMODEL; d += blockDim.x) {
        int k2 = d & ~1;                              // 2*i
        float div = expf((float)k2 * c);
        float ang = (float)t * div;
        float pe  = (d & 1) ? cosf(ang) : sinf(ang);
        out[(size_t)row*DMODEL + d] = e[d] * 27.712812921102035f + pe; // sqrt(768)
    }
}

// ---------------- layernorm ----------------
__device__ __forceinline__ float blockReduceSum(float v)
{
    __shared__ float sh[9];
    int lane = threadIdx.x & 31, w = threadIdx.x >> 5;
    #pragma unroll
    for (int o = 16; o; o >>= 1) v += __shfl_xor_sync(0xffffffffu, v, o);
    __syncthreads();
    if (lane == 0) sh[w] = v;
    __syncthreads();
    if (threadIdx.x == 0) {
        float t = 0.f;
        #pragma unroll
        for (int i = 0; i < 8; i++) t += sh[i];
        sh[8] = t;
    }
    __syncthreads();
    return sh[8];
}

__global__ __launch_bounds__(256) void ln_kernel(const float* __restrict__ X,
                                                 const float* __restrict__ gam,
                                                 const float* __restrict__ bet,
                                                 float* __restrict__ Y)
{
    int row = blockIdx.x;
    const float* x = X + (size_t)row * DMODEL;
    float s = 0.f;
    for (int d = threadIdx.x; d < DMODEL; d += 256) s += x[d];
    s = blockReduceSum(s);
    float mean = s / (float)DMODEL;
    float v = 0.f;
    for (int d = threadIdx.x; d < DMODEL; d += 256) { float t = x[d] - mean; v += t * t; }
    v = blockReduceSum(v);
    float inv = rsqrtf(v / (float)DMODEL + 1e-6f);
    for (int d = threadIdx.x; d < DMODEL; d += 256)
        Y[(size_t)row*DMODEL + d] = (x[d] - mean) * inv * gam[d] + bet[d];
}

// ---------------- GEMM: C[M,N] = A[M,K] @ W[N,K]^T (+bias)(+gelu)(+resid) ----------------
// BM=BN=128, BK=8, 256 threads, 8x8 per thread. All shapes divide evenly here.
template<bool BIAS, bool RESID, bool GELU>
__global__ __launch_bounds__(256) void gemm_nt(
    const float* __restrict__ A, const float* __restrict__ W,
    const float* __restrict__ bias, const float* __restrict__ Rm,
    float* __restrict__ C, int M, int N, int K)
{
    __shared__ float As[8][128];
    __shared__ float Bs[8][128];
    int tid  = threadIdx.x;
    int brow = blockIdx.y * 128, bcol = blockIdx.x * 128;
    int tr = tid >> 4, tc = tid & 15;
    int lr = tid >> 1, lk = (tid & 1) * 4;
    const float* Ap = A + (size_t)(brow + lr) * K + lk;
    const float* Wp = W + (size_t)(bcol + lr) * K + lk;

    float acc[8][8];
    #pragma unroll
    for (int i = 0; i < 8; i++)
        #pragma unroll
        for (int j = 0; j < 8; j++) acc[i][j] = 0.f;

    for (int k0 = 0; k0 < K; k0 += 8) {
        float4 a4 = *(const float4*)(Ap + k0);
        float4 w4 = *(const float4*)(Wp + k0);
        __syncthreads();
        As[lk+0][lr] = a4.x; As[lk+1][lr] = a4.y; As[lk+2][lr] = a4.z; As[lk+3][lr] = a4.w;
        Bs[lk+0][lr] = w4.x; Bs[lk+1][lr] = w4.y; Bs[lk+2][lr] = w4.z; Bs[lk+3][lr] = w4.w;
        __syncthreads();
        #pragma unroll
        for (int kk = 0; kk < 8; kk++) {
            float ra[8], rb[8];
            *(float4*)(ra)   = *(const float4*)&As[kk][tr*8];
            *(float4*)(ra+4) = *(const float4*)&As[kk][tr*8+4];
            *(float4*)(rb)   = *(const float4*)&Bs[kk][tc*8];
            *(float4*)(rb+4) = *(const float4*)&Bs[kk][tc*8+4];
            #pragma unroll
            for (int i = 0; i < 8; i++)
                #pragma unroll
                for (int j = 0; j < 8; j++)
                    acc[i][j] += ra[i] * rb[j];
        }
    }

    #pragma unroll
    for (int i = 0; i < 8; i++) {
        int row = brow + tr*8 + i;
        #pragma unroll
        for (int j = 0; j < 8; j++) {
            int col = bcol + tc*8 + j;
            float v = acc[i][j];
            if (BIAS)  v += bias[col];
            if (GELU)  { float u = v;
                         v = 0.5f*u*(1.f + tanhf(0.7978845608028654f*(u + 0.044715f*u*u*u))); }
            if (RESID) v += Rm[(size_t)row*N + col];
            C[(size_t)row*N + col] = v;
        }
    }
}

// ---------------- fused flash attention (fp32, online softmax) ----------------
// grid: (qtiles=8, H, B), block 256. 64-row q tile, DH=64, smem stride 65 (conflict-free).
#define AST 65
#define ATTN_SMEM (4*64*AST*4)

template<bool CAUSAL>
__global__ __launch_bounds__(256) void attn_kernel(
    const float* __restrict__ Q, int qstride,
    const float* __restrict__ Kp, int kstride,
    const float* __restrict__ Vp, int vstride,
    const int*  __restrict__ tok, int klen,
    float* __restrict__ O, int ostride)
{
    extern __shared__ float sm[];
    float* qs = sm;
    float* ks = sm + 64*AST;
    float* vs = sm + 2*64*AST;
    float* ps = sm + 3*64*AST;
    __shared__ int smask[64];

    int tid = threadIdx.x;
    int qt = blockIdx.x, h = blockIdx.y, b = blockIdx.z;
    int qbase = qt * 64;

    int lrow = tid >> 2;            // 0..63 (tile loads)
    int lcol = (tid & 3) * 16;      // 0,16,32,48

    // load q tile (scaled by DH^-0.5)
    {
        const float* qp = Q + (size_t)(b*TLEN_ + qbase + lrow)*qstride + h*DH_ + lcol;
        #pragma unroll
        for (int w = 0; w < 4; w++) {
            float4 v = *(const float4*)(qp + w*4);
            float* d = qs + lrow*AST + lcol + w*4;
            d[0] = v.x*0.125f; d[1] = v.y*0.125f; d[2] = v.z*0.125f; d[3] = v.w*0.125f;
        }
    }

    int r0     = (tid >> 4) * 4;    // 4 rows per thread
    int lane16 = tid & 15;          // col base; cols lane16 + 16*jj

    float m[4], l[4], acc[4][4];
    #pragma unroll
    for (int i = 0; i < 4; i++) {
        m[i] = -INFINITY; l[i] = 0.f;
        #pragma unroll
        for (int j = 0; j < 4; j++) acc[i][j] = 0.f;
    }

    int nkt = CAUSAL ? (qt + 1) : (klen / 64);
    for (int kt = 0; kt < nkt; kt++) {
        __syncthreads();
        // load k,v tiles + key pad mask
        {
            const float* kp = Kp + (size_t)(b*klen + kt*64 + lrow)*kstride + h*DH_ + lcol;
            const float* vp = Vp + (size_t)(b*klen + kt*64 + lrow)*vstride + h*DH_ + lcol;
            #pragma unroll
            for (int w = 0; w < 4; w++) {
                float4 k4 = *(const float4*)(kp + w*4);
                float* dk = ks + lrow*AST + lcol + w*4;
                dk[0]=k4.x; dk[1]=k4.y; dk[2]=k4.z; dk[3]=k4.w;
                float4 v4 = *(const float4*)(vp + w*4);
                float* dv = vs + lrow*AST + lcol + w*4;
                dv[0]=v4.x; dv[1]=v4.y; dv[2]=v4.z; dv[3]=v4.w;
            }
            if (tid < 64) smask[tid] = (tok[b*klen + kt*64 + tid] == 0);
        }
        __syncthreads();

        // scores s[i][ii]: row r0+i, col lane16+16*ii
        float s[4][4];
        #pragma unroll
        for (int i = 0; i < 4; i++)
            #pragma unroll
            for (int j = 0; j < 4; j++) s[i][j] = 0.f;

        #pragma unroll 8
        for (int j = 0; j < 64; j++) {
            float ra[4], rb[4];
            #pragma unroll
            for (int i = 0; i < 4; i++) ra[i] = qs[(r0+i)*AST + j];
            #pragma unroll
            for (int ii = 0; ii < 4; ii++) rb[ii] = ks[(lane16 + 16*ii)*AST + j];
            #pragma unroll
            for (int i = 0; i < 4; i++)
                #pragma unroll
                for (int ii = 0; ii < 4; ii++) s[i][ii] += ra[i] * rb[ii];
        }

        // masking: key pad + causal; replace (not add) with -1e18 like the reference
        #pragma unroll
        for (int i = 0; i < 4; i++) {
            int qg = qbase + r0 + i;
            #pragma unroll
            for (int ii = 0; ii < 4; ii++) {
                int cl = lane16 + 16*ii;
                int kg = kt*64 + cl;
                bool msk = (smask[cl] != 0) || (CAUSAL && kg > qg);
                if (msk) s[i][ii] = -1e18f;
            }
        }

        // online softmax (rows shared by 16 consecutive lanes)
        #pragma unroll
        for (int i = 0; i < 4; i++) {
            float rm = fmaxf(fmaxf(s[i][0], s[i][1]), fmaxf(s[i][2], s[i][3]));
            #pragma unroll
            for (int o = 1; o < 16; o <<= 1) rm = fmaxf(rm, __shfl_xor_sync(0xffffffffu, rm, o));
            float nm    = fmaxf(m[i], rm);
            float alpha = expf(m[i] - nm);
            float rs = 0.f;
            #pragma unroll
            for (int ii = 0; ii < 4; ii++) {
                float p = expf(s[i][ii] - nm);
                s[i][ii] = p; rs += p;
            }
            #pragma unroll
            for (int o = 1; o < 16; o <<= 1) rs += __shfl_xor_sync(0xffffffffu, rs, o);
            l[i] = l[i]*alpha + rs;
            m[i] = nm;
            #pragma unroll
            for (int j = 0; j < 4; j++) acc[i][j] *= alpha;
        }

        // write p to smem
        #pragma unroll
        for (int i = 0; i < 4; i++)
            #pragma unroll
            for (int ii = 0; ii < 4; ii++)
                ps[(r0+i)*AST + lane16 + 16*ii] = s[i][ii];
        __syncthreads();

        // acc += p @ v
        #pragma unroll 8
        for (int c = 0; c < 64; c++) {
            float pv[4], vv[4];
            #pragma unroll
            for (int i = 0; i < 4; i++) pv[i] = ps[(r0+i)*AST + c];
            #pragma unroll
            for (int j = 0; j < 4; j++) vv[j] = vs[c*AST + lane16 + 16*j];
            #pragma unroll
            for (int i = 0; i < 4; i++)
                #pragma unroll
                for (int j = 0; j < 4; j++) acc[i][j] += pv[i] * vv[j];
        }
    }

    // write out = acc / l
    #pragma unroll
    for (int i = 0; i < 4; i++) {
        float inv = 1.f / l[i];
        size_t base = (size_t)(b*TLEN_ + qbase + r0 + i)*ostride + h*DH_;
        #pragma unroll
        for (int j = 0; j < 4; j++)
            O[base + lane16 + 16*j] = acc[i][j] * inv;
    }
}

// ---------------- host orchestration ----------------
extern "C" void kernel_launch(void* const* d_in, const int* in_sizes, int n_in,
                              void* d_out, int out_size)
{
    (void)in_sizes; (void)n_in; (void)out_size;
    const int*   tgt    = (const int*)  d_in[0];
    const int*   src    = (const int*)  d_in[1];
    const float* memory = (const float*)d_in[2];
    const float* emb    = (const float*)d_in[3];
    const float* sa_w   = (const float*)d_in[4];
    const float* sa_b   = (const float*)d_in[5];
    const float* ca_w   = (const float*)d_in[6];
    const float* ca_b   = (const float*)d_in[7];
    const float* ln_g   = (const float*)d_in[8];
    const float* ln_b   = (const float*)d_in[9];
    const float* ff_w1  = (const float*)d_in[10];
    const float* ff_b1  = (const float*)d_in[11];
    const float* ff_w2  = (const float*)d_in[12];
    const float* ff_b2  = (const float*)d_in[13];
    const float* out_g  = (const float*)d_in[14];
    const float* out_b  = (const float*)d_in[15];
    float* out = (float*)d_out;

    float *res, *res2, *lnb, *qkv, *kv, *ctx, *ff;
    cudaGetSymbolAddress((void**)&res,  g_res);
    cudaGetSymbolAddress((void**)&res2, g_res2);
    cudaGetSymbolAddress((void**)&lnb,  g_lnb);
    cudaGetSymbolAddress((void**)&qkv,  g_qkv);
    cudaGetSymbolAddress((void**)&kv,   g_kv);
    cudaGetSymbolAddress((void**)&ctx,  g_ctx);
    cudaGetSymbolAddress((void**)&ff,   g_ff);

    cudaFuncSetAttribute(attn_kernel<true>,  cudaFuncAttributeMaxDynamicSharedMemorySize, ATTN_SMEM);
    cudaFuncSetAttribute(attn_kernel<false>, cudaFuncAttributeMaxDynamicSharedMemorySize, ATTN_SMEM);

    embed_kernel<<<BT_, 256>>>(tgt, emb, res);

    const dim3 g768 (DMODEL/128, BT_/128);   // N=768
    const dim3 g1536(2*DMODEL/128, BS_/128);
    const dim3 g2304(3*DMODEL/128, BT_/128);
    const dim3 g3072(DFF_/128, BT_/128);
    const dim3 attn_grid(TLEN_/64, NH, BB);

    for (int i = 0; i < NL; i++) {
        const float* saw = sa_w + (size_t)i*4*DMODEL*DMODEL;
        const float* sab = sa_b + (size_t)i*4*DMODEL;
        const float* caw = ca_w + (size_t)i*4*DMODEL*DMODEL;
        const float* cab = ca_b + (size_t)i*4*DMODEL;
        const float* lg  = ln_g + (size_t)i*3*DMODEL;
        const float* lb  = ln_b + (size_t)i*3*DMODEL;

        // ----- self attention -----
        ln_kernel<<<BT_, 256>>>(res, lg, lb, lnb);
        gemm_nt<true,false,false><<<g2304, 256>>>(lnb, saw, sab, nullptr, qkv,
                                                  BT_, 3*DMODEL, DMODEL);
        attn_kernel<true><<<attn_grid, 256, ATTN_SMEM>>>(
            qkv, 3*DMODEL, qkv + DMODEL, 3*DMODEL, qkv + 2*DMODEL, 3*DMODEL,
            tgt, TLEN_, ctx, DMODEL);
        gemm_nt<true,true,false><<<g768, 256>>>(ctx, saw + (size_t)3*DMODEL*DMODEL,
                                                sab + 3*DMODEL, res, res2,
                                                BT_, DMODEL, DMODEL);

        // ----- cross attention -----
        ln_kernel<<<BT_, 256>>>(res2, lg + DMODEL, lb + DMODEL, lnb);
        gemm_nt<true,false,false><<<g768, 256>>>(lnb, caw, cab, nullptr, qkv,
                                                 BT_, DMODEL, DMODEL);
        gemm_nt<true,false,false><<<g1536, 256>>>(memory, caw + (size_t)DMODEL*DMODEL,
                                                  cab + DMODEL, nullptr, kv,
                                                  BS_, 2*DMODEL, DMODEL);
        attn_kernel<false><<<attn_grid, 256, ATTN_SMEM>>>(
            qkv, DMODEL, kv, 2*DMODEL, kv + DMODEL, 2*DMODEL,
            src, SLEN_, ctx, DMODEL);
        gemm_nt<true,true,false><<<g768, 256>>>(ctx, caw + (size_t)3*DMODEL*DMODEL,
                                                cab + 3*DMODEL, res2, res,
                                                BT_, DMODEL, DMODEL);

        // ----- FFN -----
        ln_kernel<<<BT_, 256>>>(res, lg + 2*DMODEL, lb + 2*DMODEL, lnb);
        gemm_nt<true,false,true><<<g3072, 256>>>(lnb, ff_w1 + (size_t)i*DFF_*DMODEL,
                                                 ff_b1 + (size_t)i*DFF_, nullptr, ff,
                                                 BT_, DFF_, DMODEL);
        gemm_nt<true,true,false><<<g768, 256>>>(ff, ff_w2 + (size_t)i*DMODEL*DFF_,
                                                ff_b2 + (size_t)i*DMODEL, res, res2,
                                                BT_, DMODEL, DFF_);

        // residual stream now in res2
        float* tmp = res; res = res2; res2 = tmp;
    }

    ln_kernel<<<BT_, 256>>>(res, out_g, out_b, out);
}

// round 2
// speedup vs baseline: 2.1981x; 2.1981x over previous
#include <cuda_runtime.h>
#include <math.h>
#include <stdint.h>

// ---------------- problem constants ----------------
#define NL    6
#define DMODEL 768
#define NH    12
#define DFF_  3072
#define BB    8
#define TLEN_ 512
#define SLEN_ 512
#define DH_   64
#define BT_   (BB*TLEN_)   // 4096 target tokens
#define BS_   (BB*SLEN_)   // 4096 source tokens

// ---------------- scratch (device globals: allocation-free) ----------------
__device__ float g_res [BT_*DMODEL];
__device__ float g_res2[BT_*DMODEL];
__device__ float g_lnb [BT_*DMODEL];
__device__ float g_qkv [BT_*3*DMODEL];
__device__ float g_kv  [BS_*2*DMODEL];
__device__ float g_ctx [BT_*DMODEL];
__device__ float g_ff  [BT_*DFF_];

// ---------------- embedding + positional encoding ----------------
__global__ void embed_kernel(const int* __restrict__ tgt,
                             const float* __restrict__ emb,
                             float* __restrict__ out)
{
    int row = blockIdx.x;              // b*T + t
    int t   = row & (TLEN_ - 1);
    int tok = tgt[row];
    const float* e = emb + (size_t)tok * DMODEL;
    const float c = (float)(-9.210340371976184 / (double)DMODEL);  // -ln(10000)/D
    for (int d = threadIdx.x; d < DMODEL; d += blockDim.x) {
        int k2 = d & ~1;                              // 2*i
        float div = expf((float)k2 * c);
        float ang = (float)t * div;
        float pe  = (d & 1) ? cosf(ang) : sinf(ang);
        out[(size_t)row*DMODEL + d] = e[d] * 27.712812921102035f + pe; // sqrt(768)
    }
}

// ---------------- layernorm ----------------
__device__ __forceinline__ float blockReduceSum(float v)
{
    __shared__ float sh[9];
    int lane = threadIdx.x & 31, w = threadIdx.x >> 5;
    #pragma unroll
    for (int o = 16; o; o >>= 1) v += __shfl_xor_sync(0xffffffffu, v, o);
    __syncthreads();
    if (lane == 0) sh[w] = v;
    __syncthreads();
    if (threadIdx.x == 0) {
        float t = 0.f;
        #pragma unroll
        for (int i = 0; i < 8; i++) t += sh[i];
        sh[8] = t;
    }
    __syncthreads();
    return sh[8];
}

__global__ __launch_bounds__(256) void ln_kernel(const float* __restrict__ X,
                                                 const float* __restrict__ gam,
                                                 const float* __restrict__ bet,
                                                 float* __restrict__ Y)
{
    int row = blockIdx.x;
    const float* x = X + (size_t)row * DMODEL;
    float s = 0.f;
    for (int d = threadIdx.x; d < DMODEL; d += 256) s += x[d];
    s = blockReduceSum(s);
    float mean = s / (float)DMODEL;
    float v = 0.f;
    for (int d = threadIdx.x; d < DMODEL; d += 256) { float t = x[d] - mean; v += t * t; }
    v = blockReduceSum(v);
    float inv = rsqrtf(v / (float)DMODEL + 1e-6f);
    for (int d = threadIdx.x; d < DMODEL; d += 256)
        Y[(size_t)row*DMODEL + d] = (x[d] - mean) * inv * gam[d] + bet[d];
}

// ---------------- TF32 tensor-core GEMM ----------------
// C[M,N] = A[M,K] @ W[N,K]^T (+bias)(+gelu)(+resid)
// 128x128 block tile, BK=32, 256 threads = 8 warps, warp tile 32x64.
// mma.sync.aligned.m16n8k8.row.col.f32.tf32.tf32.f32

__device__ __forceinline__ float to_tf32(float x)
{
    float r;
    asm("cvt.rna.tf32.f32 %0, %1;" : "=f"(r) : "f"(x));
    return r;
}

__device__ __forceinline__ void mma_tf32(float c[4], const uint32_t a[4], const uint32_t b[2])
{
    asm volatile(
        "mma.sync.aligned.m16n8k8.row.col.f32.tf32.tf32.f32 "
        "{%0,%1,%2,%3}, {%4,%5,%6,%7}, {%8,%9}, {%0,%1,%2,%3};"
        : "+f"(c[0]), "+f"(c[1]), "+f"(c[2]), "+f"(c[3])
        : "r"(a[0]), "r"(a[1]), "r"(a[2]), "r"(a[3]), "r"(b[0]), "r"(b[1]));
}

#define SST 36   // smem row stride (floats): bank = (4*gid+tig)%32, conflict-free

template<bool BIAS, bool RESID, bool GELU>
__global__ __launch_bounds__(256) void gemm_tc(
    const float* __restrict__ A, const float* __restrict__ W,
    const float* __restrict__ bias, const float* __restrict__ Rm,
    float* __restrict__ C, int M, int N, int K)
{
    __shared__ float As[128][SST];
    __shared__ float Bs[128][SST];

    const int tid  = threadIdx.x;
    const int warp = tid >> 5, lane = tid & 31;
    const int gid  = lane >> 2, tig = lane & 3;
    const int brow = blockIdx.y * 128, bcol = blockIdx.x * 128;
    const int wr   = (warp >> 1) * 32;   // warp row offset in tile (0,32,64,96)
    const int wc   = (warp & 1) * 64;    // warp col offset in tile (0,64)

    // global load mapping: each thread loads 4 float4 of A and 4 of W per iter
    const int grow = tid >> 1;           // 0..127
    const int gk   = (tid & 1) * 16;     // 0 or 16
    const float* Ap = A + (size_t)(brow + grow) * K + gk;
    const float* Wp = W + (size_t)(bcol + grow) * K + gk;

    float acc[2][8][4];
    #pragma unroll
    for (int mt = 0; mt < 2; mt++)
        #pragma unroll
        for (int nt = 0; nt < 8; nt++)
            #pragma unroll
            for (int r = 0; r < 4; r++) acc[mt][nt][r] = 0.f;

    for (int k0 = 0; k0 < K; k0 += 32) {
        float4 av[4], wv[4];
        #pragma unroll
        for (int j = 0; j < 4; j++) {
            av[j] = *(const float4*)(Ap + k0 + j*4);
            wv[j] = *(const float4*)(Wp + k0 + j*4);
        }
        __syncthreads();
        #pragma unroll
        for (int j = 0; j < 4; j++) {
            As[grow][gk + j*4 + 0] = to_tf32(av[j].x);
            As[grow][gk + j*4 + 1] = to_tf32(av[j].y);
            As[grow][gk + j*4 + 2] = to_tf32(av[j].z);
            As[grow][gk + j*4 + 3] = to_tf32(av[j].w);
            Bs[grow][gk + j*4 + 0] = to_tf32(wv[j].x);
            Bs[grow][gk + j*4 + 1] = to_tf32(wv[j].y);
            Bs[grow][gk + j*4 + 2] = to_tf32(wv[j].z);
            Bs[grow][gk + j*4 + 3] = to_tf32(wv[j].w);
        }
        __syncthreads();

        #pragma unroll
        for (int ks = 0; ks < 4; ks++) {
            const int kb = ks * 8;
            uint32_t afr[2][4], bfr[8][2];
            #pragma unroll
            for (int mt = 0; mt < 2; mt++) {
                int r0 = wr + mt*16 + gid;
                afr[mt][0] = __float_as_uint(As[r0    ][kb + tig    ]);
                afr[mt][1] = __float_as_uint(As[r0 + 8][kb + tig    ]);
                afr[mt][2] = __float_as_uint(As[r0    ][kb + tig + 4]);
                afr[mt][3] = __float_as_uint(As[r0 + 8][kb + tig + 4]);
            }
            #pragma unroll
            for (int nt = 0; nt < 8; nt++) {
                int c0 = wc + nt*8 + gid;
                bfr[nt][0] = __float_as_uint(Bs[c0][kb + tig    ]);
                bfr[nt][1] = __float_as_uint(Bs[c0][kb + tig + 4]);
            }
            #pragma unroll
            for (int mt = 0; mt < 2; mt++)
                #pragma unroll
                for (int nt = 0; nt < 8; nt++)
                    mma_tf32(acc[mt][nt], afr[mt], bfr[nt]);
        }
    }

    // epilogue: c0,c1 -> (row gid, cols 2*tig,2*tig+1); c2,c3 -> row gid+8
    #pragma unroll
    for (int mt = 0; mt < 2; mt++) {
        #pragma unroll
        for (int half = 0; half < 2; half++) {
            int row = brow + wr + mt*16 + gid + half*8;
            #pragma unroll
            for (int nt = 0; nt < 8; nt++) {
                int col = bcol + wc + nt*8 + 2*tig;
                float v0 = acc[mt][nt][half*2 + 0];
                float v1 = acc[mt][nt][half*2 + 1];
                if (BIAS) { v0 += bias[col]; v1 += bias[col+1]; }
                if (GELU) {
                    float u0 = v0, u1 = v1;
                    v0 = 0.5f*u0*(1.f + tanhf(0.7978845608028654f*(u0 + 0.044715f*u0*u0*u0)));
                    v1 = 0.5f*u1*(1.f + tanhf(0.7978845608028654f*(u1 + 0.044715f*u1*u1*u1)));
                }
                if (RESID) {
                    v0 += Rm[(size_t)row*N + col];
                    v1 += Rm[(size_t)row*N + col + 1];
                }
                *(float2*)&C[(size_t)row*N + col] = make_float2(v0, v1);
            }
        }
    }
}

// ---------------- fused flash attention (fp32, online softmax) ----------------
// grid: (qtiles=8, H, B), block 256. 64-row q tile, DH=64, smem stride 65 (conflict-free).
#define AST 65
#define ATTN_SMEM (4*64*AST*4)

template<bool CAUSAL>
__global__ __launch_bounds__(256) void attn_kernel(
    const float* __restrict__ Q, int qstride,
    const float* __restrict__ Kp, int kstride,
    const float* __restrict__ Vp, int vstride,
    const int*  __restrict__ tok, int klen,
    float* __restrict__ O, int ostride)
{
    extern __shared__ float sm[];
    float* qs = sm;
    float* ks = sm + 64*AST;
    float* vs = sm + 2*64*AST;
    float* ps = sm + 3*64*AST;
    __shared__ int smask[64];

    int tid = threadIdx.x;
    int qt = blockIdx.x, h = blockIdx.y, b = blockIdx.z;
    int qbase = qt * 64;

    int lrow = tid >> 2;            // 0..63 (tile loads)
    int lcol = (tid & 3) * 16;      // 0,16,32,48

    // load q tile (scaled by DH^-0.5)
    {
        const float* qp = Q + (size_t)(b*TLEN_ + qbase + lrow)*qstride + h*DH_ + lcol;
        #pragma unroll
        for (int w = 0; w < 4; w++) {
            float4 v = *(const float4*)(qp + w*4);
            float* d = qs + lrow*AST + lcol + w*4;
            d[0] = v.x*0.125f; d[1] = v.y*0.125f; d[2] = v.z*0.125f; d[3] = v.w*0.125f;
        }
    }

    int r0     = (tid >> 4) * 4;    // 4 rows per thread
    int lane16 = tid & 15;          // col base; cols lane16 + 16*jj

    float m[4], l[4], acc[4][4];
    #pragma unroll
    for (int i = 0; i < 4; i++) {
        m[i] = -INFINITY; l[i] = 0.f;
        #pragma unroll
        for (int j = 0; j < 4; j++) acc[i][j] = 0.f;
    }

    int nkt = CAUSAL ? (qt + 1) : (klen / 64);
    for (int kt = 0; kt < nkt; kt++) {
        __syncthreads();
        // load k,v tiles + key pad mask
        {
            const float* kp = Kp + (size_t)(b*klen + kt*64 + lrow)*kstride + h*DH_ + lcol;
            const float* vp = Vp + (size_t)(b*klen + kt*64 + lrow)*vstride + h*DH_ + lcol;
            #pragma unroll
            for (int w = 0; w < 4; w++) {
                float4 k4 = *(const float4*)(kp + w*4);
                float* dk = ks + lrow*AST + lcol + w*4;
                dk[0]=k4.x; dk[1]=k4.y; dk[2]=k4.z; dk[3]=k4.w;
                float4 v4 = *(const float4*)(vp + w*4);
                float* dv = vs + lrow*AST + lcol + w*4;
                dv[0]=v4.x; dv[1]=v4.y; dv[2]=v4.z; dv[3]=v4.w;
            }
            if (tid < 64) smask[tid] = (tok[b*klen + kt*64 + tid] == 0);
        }
        __syncthreads();

        // scores s[i][ii]: row r0+i, col lane16+16*ii
        float s[4][4];
        #pragma unroll
        for (int i = 0; i < 4; i++)
            #pragma unroll
            for (int j = 0; j < 4; j++) s[i][j] = 0.f;

        #pragma unroll 8
        for (int j = 0; j < 64; j++) {
            float ra[4], rb[4];
            #pragma unroll
            for (int i = 0; i < 4; i++) ra[i] = qs[(r0+i)*AST + j];
            #pragma unroll
            for (int ii = 0; ii < 4; ii++) rb[ii] = ks[(lane16 + 16*ii)*AST + j];
            #pragma unroll
            for (int i = 0; i < 4; i++)
                #pragma unroll
                for (int ii = 0; ii < 4; ii++) s[i][ii] += ra[i] * rb[ii];
        }

        // masking: key pad + causal; replace (not add) with -1e18 like the reference
        #pragma unroll
        for (int i = 0; i < 4; i++) {
            int qg = qbase + r0 + i;
            #pragma unroll
            for (int ii = 0; ii < 4; ii++) {
                int cl = lane16 + 16*ii;
                int kg = kt*64 + cl;
                bool msk = (smask[cl] != 0) || (CAUSAL && kg > qg);
                if (msk) s[i][ii] = -1e18f;
            }
        }

        // online softmax (rows shared by 16 consecutive lanes)
        #pragma unroll
        for (int i = 0; i < 4; i++) {
            float rm = fmaxf(fmaxf(s[i][0], s[i][1]), fmaxf(s[i][2], s[i][3]));
            #pragma unroll
            for (int o = 1; o < 16; o <<= 1) rm = fmaxf(rm, __shfl_xor_sync(0xffffffffu, rm, o));
            float nm    = fmaxf(m[i], rm);
            float alpha = expf(m[i] - nm);
            float rs = 0.f;
            #pragma unroll
            for (int ii = 0; ii < 4; ii++) {
                float p = expf(s[i][ii] - nm);
                s[i][ii] = p; rs += p;
            }
            #pragma unroll
            for (int o = 1; o < 16; o <<= 1) rs += __shfl_xor_sync(0xffffffffu, rs, o);
            l[i] = l[i]*alpha + rs;
            m[i] = nm;
            #pragma unroll
            for (int j = 0; j < 4; j++) acc[i][j] *= alpha;
        }

        // write p to smem
        #pragma unroll
        for (int i = 0; i < 4; i++)
            #pragma unroll
            for (int ii = 0; ii < 4; ii++)
                ps[(r0+i)*AST + lane16 + 16*ii] = s[i][ii];
        __syncthreads();

        // acc += p @ v
        #pragma unroll 8
        for (int c = 0; c < 64; c++) {
            float pv[4], vv[4];
            #pragma unroll
            for (int i = 0; i < 4; i++) pv[i] = ps[(r0+i)*AST + c];
            #pragma unroll
            for (int j = 0; j < 4; j++) vv[j] = vs[c*AST + lane16 + 16*j];
            #pragma unroll
            for (int i = 0; i < 4; i++)
                #pragma unroll
                for (int j = 0; j < 4; j++) acc[i][j] += pv[i] * vv[j];
        }
    }

    // write out = acc / l
    #pragma unroll
    for (int i = 0; i < 4; i++) {
        float inv = 1.f / l[i];
        size_t base = (size_t)(b*TLEN_ + qbase + r0 + i)*ostride + h*DH_;
        #pragma unroll
        for (int j = 0; j < 4; j++)
            O[base + lane16 + 16*j] = acc[i][j] * inv;
    }
}

// ---------------- host orchestration ----------------
extern "C" void kernel_launch(void* const* d_in, const int* in_sizes, int n_in,
                              void* d_out, int out_size)
{
    (void)in_sizes; (void)n_in; (void)out_size;
    const int*   tgt    = (const int*)  d_in[0];
    const int*   src    = (const int*)  d_in[1];
    const float* memory = (const float*)d_in[2];
    const float* emb    = (const float*)d_in[3];
    const float* sa_w   = (const float*)d_in[4];
    const float* sa_b   = (const float*)d_in[5];
    const float* ca_w   = (const float*)d_in[6];
    const float* ca_b   = (const float*)d_in[7];
    const float* ln_g   = (const float*)d_in[8];
    const float* ln_b   = (const float*)d_in[9];
    const float* ff_w1  = (const float*)d_in[10];
    const float* ff_b1  = (const float*)d_in[11];
    const float* ff_w2  = (const float*)d_in[12];
    const float* ff_b2  = (const float*)d_in[13];
    const float* out_g  = (const float*)d_in[14];
    const float* out_b  = (const float*)d_in[15];
    float* out = (float*)d_out;

    float *res, *res2, *lnb, *qkv, *kv, *ctx, *ff;
    cudaGetSymbolAddress((void**)&res,  g_res);
    cudaGetSymbolAddress((void**)&res2, g_res2);
    cudaGetSymbolAddress((void**)&lnb,  g_lnb);
    cudaGetSymbolAddress((void**)&qkv,  g_qkv);
    cudaGetSymbolAddress((void**)&kv,   g_kv);
    cudaGetSymbolAddress((void**)&ctx,  g_ctx);
    cudaGetSymbolAddress((void**)&ff,   g_ff);

    cudaFuncSetAttribute(attn_kernel<true>,  cudaFuncAttributeMaxDynamicSharedMemorySize, ATTN_SMEM);
    cudaFuncSetAttribute(attn_kernel<false>, cudaFuncAttributeMaxDynamicSharedMemorySize, ATTN_SMEM);

    embed_kernel<<<BT_, 256>>>(tgt, emb, res);

    const dim3 g768 (DMODEL/128, BT_/128);   // N=768
    const dim3 g1536(2*DMODEL/128, BS_/128);
    const dim3 g2304(3*DMODEL/128, BT_/128);
    const dim3 g3072(DFF_/128, BT_/128);
    const dim3 attn_grid(TLEN_/64, NH, BB);

    for (int i = 0; i < NL; i++) {
        const float* saw = sa_w + (size_t)i*4*DMODEL*DMODEL;
        const float* sab = sa_b + (size_t)i*4*DMODEL;
        const float* caw = ca_w + (size_t)i*4*DMODEL*DMODEL;
        const float* cab = ca_b + (size_t)i*4*DMODEL;
        const float* lg  = ln_g + (size_t)i*3*DMODEL;
        const float* lb  = ln_b + (size_t)i*3*DMODEL;

        // ----- self attention -----
        ln_kernel<<<BT_, 256>>>(res, lg, lb, lnb);
        gemm_tc<true,false,false><<<g2304, 256>>>(lnb, saw, sab, nullptr, qkv,
                                                  BT_, 3*DMODEL, DMODEL);
        attn_kernel<true><<<attn_grid, 256, ATTN_SMEM>>>(
            qkv, 3*DMODEL, qkv + DMODEL, 3*DMODEL, qkv + 2*DMODEL, 3*DMODEL,
            tgt, TLEN_, ctx, DMODEL);
        gemm_tc<true,true,false><<<g768, 256>>>(ctx, saw + (size_t)3*DMODEL*DMODEL,
                                                sab + 3*DMODEL, res, res2,
                                                BT_, DMODEL, DMODEL);

        // ----- cross attention -----
        ln_kernel<<<BT_, 256>>>(res2, lg + DMODEL, lb + DMODEL, lnb);
        gemm_tc<true,false,false><<<g768, 256>>>(lnb, caw, cab, nullptr, qkv,
                                                 BT_, DMODEL, DMODEL);
        gemm_tc<true,false,false><<<g1536, 256>>>(memory, caw + (size_t)DMODEL*DMODEL,
                                                  cab + DMODEL, nullptr, kv,
                                                  BS_, 2*DMODEL, DMODEL);
        attn_kernel<false><<<attn_grid, 256, ATTN_SMEM>>>(
            qkv, DMODEL, kv, 2*DMODEL, kv + DMODEL, 2*DMODEL,
            src, SLEN_, ctx, DMODEL);
        gemm_tc<true,true,false><<<g768, 256>>>(ctx, caw + (size_t)3*DMODEL*DMODEL,
                                                cab + 3*DMODEL, res2, res,
                                                BT_, DMODEL, DMODEL);

        // ----- FFN -----
        ln_kernel<<<BT_, 256>>>(res, lg + 2*DMODEL, lb + 2*DMODEL, lnb);
        gemm_tc<true,false,true><<<g3072, 256>>>(lnb, ff_w1 + (size_t)i*DFF_*DMODEL,
                                                 ff_b1 + (size_t)i*DFF_, nullptr, ff,
                                                 BT_, DFF_, DMODEL);
        gemm_tc<true,true,false><<<g768, 256>>>(ff, ff_w2 + (size_t)i*DMODEL*DFF_,
                                                ff_b2 + (size_t)i*DMODEL, res, res2,
                                                BT_, DMODEL, DFF_);

        // residual stream now in res2
        float* tmp = res; res = res2; res2 = tmp;
    }

    ln_kernel<<<BT_, 256>>>(res, out_g, out_b, out);
}

// round 3
// speedup vs baseline: 2.2217x; 1.0107x over previous
#include <cuda_runtime.h>
#include <math.h>
#include <stdint.h>

// ---------------- problem constants ----------------
#define NL    6
#define DMODEL 768
#define NH    12
#define DFF_  3072
#define BB    8
#define TLEN_ 512
#define SLEN_ 512
#define DH_   64
#define BT_   (BB*TLEN_)   // 4096 target tokens
#define BS_   (BB*SLEN_)   // 4096 source tokens

// ---------------- scratch (device globals: allocation-free) ----------------
__device__ float g_res [BT_*DMODEL];
__device__ float g_res2[BT_*DMODEL];
__device__ float g_lnb [BT_*DMODEL];
__device__ float g_qkv [BT_*3*DMODEL];
__device__ float g_kv  [BS_*2*DMODEL];
__device__ float g_ctx [BT_*DMODEL];
__device__ float g_ff  [BT_*DFF_];

// ---------------- embedding + positional encoding ----------------
__global__ void embed_kernel(const int* __restrict__ tgt,
                             const float* __restrict__ emb,
                             float* __restrict__ out)
{
    int row = blockIdx.x;              // b*T + t
    int t   = row & (TLEN_ - 1);
    int tok = tgt[row];
    const float* e = emb + (size_t)tok * DMODEL;
    const float c = (float)(-9.210340371976184 / (double)DMODEL);  // -ln(10000)/D
    for (int d = threadIdx.x; d < DMODEL; d += blockDim.x) {
        int k2 = d & ~1;                              // 2*i
        float div = expf((float)k2 * c);
        float ang = (float)t * div;
        float pe  = (d & 1) ? cosf(ang) : sinf(ang);
        out[(size_t)row*DMODEL + d] = e[d] * 27.712812921102035f + pe; // sqrt(768)
    }
}

// ---------------- layernorm ----------------
__device__ __forceinline__ float blockReduceSum(float v)
{
    __shared__ float sh[9];
    int lane = threadIdx.x & 31, w = threadIdx.x >> 5;
    #pragma unroll
    for (int o = 16; o; o >>= 1) v += __shfl_xor_sync(0xffffffffu, v, o);
    __syncthreads();
    if (lane == 0) sh[w] = v;
    __syncthreads();
    if (threadIdx.x == 0) {
        float t = 0.f;
        #pragma unroll
        for (int i = 0; i < 8; i++) t += sh[i];
        sh[8] = t;
    }
    __syncthreads();
    return sh[8];
}

__global__ __launch_bounds__(256) void ln_kernel(const float* __restrict__ X,
                                                 const float* __restrict__ gam,
                                                 const float* __restrict__ bet,
                                                 float* __restrict__ Y)
{
    int row = blockIdx.x;
    const float* x = X + (size_t)row * DMODEL;
    float s = 0.f;
    for (int d = threadIdx.x; d < DMODEL; d += 256) s += x[d];
    s = blockReduceSum(s);
    float mean = s / (float)DMODEL;
    float v = 0.f;
    for (int d = threadIdx.x; d < DMODEL; d += 256) { float t = x[d] - mean; v += t * t; }
    v = blockReduceSum(v);
    float inv = rsqrtf(v / (float)DMODEL + 1e-6f);
    for (int d = threadIdx.x; d < DMODEL; d += 256)
        Y[(size_t)row*DMODEL + d] = (x[d] - mean) * inv * gam[d] + bet[d];
}

// ---------------- TF32 helpers ----------------
__device__ __forceinline__ float to_tf32(float x)
{
    float r;
    asm("cvt.rna.tf32.f32 %0, %1;" : "=f"(r) : "f"(x));
    return r;
}

__device__ __forceinline__ void mma_tf32(float c[4], const uint32_t a[4], const uint32_t b[2])
{
    asm volatile(
        "mma.sync.aligned.m16n8k8.row.col.f32.tf32.tf32.f32 "
        "{%0,%1,%2,%3}, {%4,%5,%6,%7}, {%8,%9}, {%0,%1,%2,%3};"
        : "+f"(c[0]), "+f"(c[1]), "+f"(c[2]), "+f"(c[3])
        : "r"(a[0]), "r"(a[1]), "r"(a[2]), "r"(a[3]), "r"(b[0]), "r"(b[1]));
}

// ---------------- TF32 tensor-core GEMM ----------------
// C[M,N] = A[M,K] @ W[N,K]^T (+bias)(+gelu)(+resid)
// 128x128 block tile, BK=32, 256 threads = 8 warps, warp tile 32x64.
// Register prefetch of next k-tile overlaps LDG latency with mma compute.

#define SST 36   // smem row stride (floats): bank = (4*gid+tig)%32, conflict-free

template<bool BIAS, bool RESID, bool GELU>
__global__ __launch_bounds__(256) void gemm_tc(
    const float* __restrict__ A, const float* __restrict__ W,
    const float* __restrict__ bias, const float* __restrict__ Rm,
    float* __restrict__ C, int M, int N, int K)
{
    __shared__ float As[128][SST];
    __shared__ float Bs[128][SST];

    const int tid  = threadIdx.x;
    const int warp = tid >> 5, lane = tid & 31;
    const int gid  = lane >> 2, tig = lane & 3;
    const int brow = blockIdx.y * 128, bcol = blockIdx.x * 128;
    const int wr   = (warp >> 1) * 32;   // warp row offset (0,32,64,96)
    const int wc   = (warp & 1) * 64;    // warp col offset (0,64)

    const int grow = tid >> 1;           // 0..127
    const int gk   = (tid & 1) * 16;     // 0 or 16
    const float* Ap = A + (size_t)(brow + grow) * K + gk;
    const float* Wp = W + (size_t)(bcol + grow) * K + gk;

    float acc[2][8][4];
    #pragma unroll
    for (int mt = 0; mt < 2; mt++)
        #pragma unroll
        for (int nt = 0; nt < 8; nt++)
            #pragma unroll
            for (int r = 0; r < 4; r++) acc[mt][nt][r] = 0.f;

    const int niter = K >> 5;
    float4 av[4], wv[4];
    #pragma unroll
    for (int j = 0; j < 4; j++) {
        av[j] = *(const float4*)(Ap + j*4);
        wv[j] = *(const float4*)(Wp + j*4);
    }

    for (int it = 0; it < niter; it++) {
        __syncthreads();
        #pragma unroll
        for (int j = 0; j < 4; j++) {
            As[grow][gk + j*4 + 0] = to_tf32(av[j].x);
            As[grow][gk + j*4 + 1] = to_tf32(av[j].y);
            As[grow][gk + j*4 + 2] = to_tf32(av[j].z);
            As[grow][gk + j*4 + 3] = to_tf32(av[j].w);
            Bs[grow][gk + j*4 + 0] = to_tf32(wv[j].x);
            Bs[grow][gk + j*4 + 1] = to_tf32(wv[j].y);
            Bs[grow][gk + j*4 + 2] = to_tf32(wv[j].z);
            Bs[grow][gk + j*4 + 3] = to_tf32(wv[j].w);
        }
        __syncthreads();

        if (it + 1 < niter) {
            const float* Apn = Ap + (it+1)*32;
            const float* Wpn = Wp + (it+1)*32;
            #pragma unroll
            for (int j = 0; j < 4; j++) {
                av[j] = *(const float4*)(Apn + j*4);
                wv[j] = *(const float4*)(Wpn + j*4);
            }
        }

        #pragma unroll
        for (int ks = 0; ks < 4; ks++) {
            const int kb = ks * 8;
            uint32_t afr[2][4];
            #pragma unroll
            for (int mt = 0; mt < 2; mt++) {
                int r0 = wr + mt*16 + gid;
                afr[mt][0] = __float_as_uint(As[r0    ][kb + tig    ]);
                afr[mt][1] = __float_as_uint(As[r0 + 8][kb + tig    ]);
                afr[mt][2] = __float_as_uint(As[r0    ][kb + tig + 4]);
                afr[mt][3] = __float_as_uint(As[r0 + 8][kb + tig + 4]);
            }
            #pragma unroll
            for (int nt = 0; nt < 8; nt++) {
                int c0 = wc + nt*8 + gid;
                uint32_t bfr[2];
                bfr[0] = __float_as_uint(Bs[c0][kb + tig    ]);
                bfr[1] = __float_as_uint(Bs[c0][kb + tig + 4]);
                mma_tf32(acc[0][nt], afr[0], bfr);
                mma_tf32(acc[1][nt], afr[1], bfr);
            }
        }
    }

    #pragma unroll
    for (int mt = 0; mt < 2; mt++) {
        #pragma unroll
        for (int half = 0; half < 2; half++) {
            int row = brow + wr + mt*16 + gid + half*8;
            #pragma unroll
            for (int nt = 0; nt < 8; nt++) {
                int col = bcol + wc + nt*8 + 2*tig;
                float v0 = acc[mt][nt][half*2 + 0];
                float v1 = acc[mt][nt][half*2 + 1];
                if (BIAS) { v0 += bias[col]; v1 += bias[col+1]; }
                if (GELU) {
                    float u0 = v0, u1 = v1;
                    v0 = 0.5f*u0*(1.f + tanhf(0.7978845608028654f*(u0 + 0.044715f*u0*u0*u0)));
                    v1 = 0.5f*u1*(1.f + tanhf(0.7978845608028654f*(u1 + 0.044715f*u1*u1*u1)));
                }
                if (RESID) {
                    v0 += Rm[(size_t)row*N + col];
                    v1 += Rm[(size_t)row*N + col + 1];
                }
                *(float2*)&C[(size_t)row*N + col] = make_float2(v0, v1);
            }
        }
    }
}

// ---------------- tensor-core flash attention (TF32 mma) ----------------
// 128 threads = 4 warps. q tile 64 rows (16 per warp), k tile 64, DH=64.
// qs/ks stride 68 (4*gid+tig conflict-free), vs stride 72 (8*tig+gid conflict-free).
// P reuses the ks buffer between S and PV phases.
#define ASTQ 68
#define ASTV 72
#define ATTN_SMEM ((2*64*ASTQ + 64*ASTV)*4)

template<bool CAUSAL>
__global__ __launch_bounds__(128) void attn_tc(
    const float* __restrict__ Q, int qstride,
    const float* __restrict__ Kp, int kstride,
    const float* __restrict__ Vp, int vstride,
    const int*  __restrict__ tok, int klen,
    float* __restrict__ O, int ostride)
{
    extern __shared__ float sm[];
    float* qs = sm;                    // [64][ASTQ]
    float* ps = sm + 64*ASTQ;          // [64][ASTQ]   K tile, reused for P
    float* vs = sm + 2*64*ASTQ;        // [64][ASTV]
    __shared__ int smask[64];

    const int tid  = threadIdx.x;
    const int warp = tid >> 5, lane = tid & 31;
    const int gid  = lane >> 2, tig = lane & 3;
    const int wrow = warp * 16;
    const int qt = blockIdx.x, h = blockIdx.y, b = blockIdx.z;
    const int qbase = qt * 64;

    // load Q tile (scaled, tf32)
    {
        int lr = tid >> 1;
        int lc = (tid & 1) * 32;
        const float* qp = Q + (size_t)(b*TLEN_ + qbase + lr)*qstride + h*DH_ + lc;
        #pragma unroll
        for (int j = 0; j < 8; j++) {
            float4 v = *(const float4*)(qp + j*4);
            float* d = qs + lr*ASTQ + lc + j*4;
            d[0] = to_tf32(v.x*0.125f); d[1] = to_tf32(v.y*0.125f);
            d[2] = to_tf32(v.z*0.125f); d[3] = to_tf32(v.w*0.125f);
        }
    }

    float m[2] = {-INFINITY, -INFINITY};
    float l[2] = {0.f, 0.f};
    float oacc[8][4];
    #pragma unroll
    for (int nt = 0; nt < 8; nt++)
        #pragma unroll
        for (int r = 0; r < 4; r++) oacc[nt][r] = 0.f;

    const int nkt = CAUSAL ? (qt + 1) : (klen >> 6);
    for (int kt = 0; kt < nkt; kt++) {
        __syncthreads();     // prev iteration fully consumed ps/vs
        {
            int lr = tid >> 1;
            int lc = (tid & 1) * 32;
            const float* kp = Kp + (size_t)(b*klen + kt*64 + lr)*kstride + h*DH_ + lc;
            const float* vp = Vp + (size_t)(b*klen + kt*64 + lr)*vstride + h*DH_ + lc;
            #pragma unroll
            for (int j = 0; j < 8; j++) {
                float4 kv4 = *(const float4*)(kp + j*4);
                float* dk = ps + lr*ASTQ + lc + j*4;
                dk[0] = to_tf32(kv4.x); dk[1] = to_tf32(kv4.y);
                dk[2] = to_tf32(kv4.z); dk[3] = to_tf32(kv4.w);
                float4 vv4 = *(const float4*)(vp + j*4);
                float* dv = vs + lr*ASTV + lc + j*4;
                dv[0] = to_tf32(vv4.x); dv[1] = to_tf32(vv4.y);
                dv[2] = to_tf32(vv4.z); dv[3] = to_tf32(vv4.w);
            }
            if (tid < 64) smask[tid] = (tok[b*klen + kt*64 + tid] == 0);
        }
        __syncthreads();

        // ---- S = Q @ K^T : sfr[nt] covers rows {gid,gid+8}+wrow, cols nt*8+{2tig,2tig+1}
        float sfr[8][4];
        #pragma unroll
        for (int nt = 0; nt < 8; nt++)
            #pragma unroll
            for (int r = 0; r < 4; r++) sfr[nt][r] = 0.f;

        #pragma unroll
        for (int ks8 = 0; ks8 < 8; ks8++) {
            const int kb = ks8*8;
            uint32_t a[4];
            a[0] = __float_as_uint(qs[(wrow+gid  )*ASTQ + kb + tig    ]);
            a[1] = __float_as_uint(qs[(wrow+gid+8)*ASTQ + kb + tig    ]);
            a[2] = __float_as_uint(qs[(wrow+gid  )*ASTQ + kb + tig + 4]);
            a[3] = __float_as_uint(qs[(wrow+gid+8)*ASTQ + kb + tig + 4]);
            #pragma unroll
            for (int nt = 0; nt < 8; nt++) {
                uint32_t bf[2];
                bf[0] = __float_as_uint(ps[(nt*8+gid)*ASTQ + kb + tig    ]);
                bf[1] = __float_as_uint(ps[(nt*8+gid)*ASTQ + kb + tig + 4]);
                mma_tf32(sfr[nt], a, bf);
            }
        }

        // ---- mask (replace with -1e18, matching reference)
        #pragma unroll
        for (int nt = 0; nt < 8; nt++) {
            #pragma unroll
            for (int e = 0; e < 4; e++) {
                int cl = nt*8 + 2*tig + (e & 1);
                int rowg = qbase + wrow + gid + (e >> 1)*8;
                int colg = kt*64 + cl;
                bool msk = (smask[cl] != 0) || (CAUSAL && colg > rowg);
                if (msk) sfr[nt][e] = -1e18f;
            }
        }

        // ---- online softmax, rows h2=0 (gid) and h2=1 (gid+8)
        #pragma unroll
        for (int h2 = 0; h2 < 2; h2++) {
            float rm = -INFINITY;
            #pragma unroll
            for (int nt = 0; nt < 8; nt++)
                rm = fmaxf(rm, fmaxf(sfr[nt][h2*2], sfr[nt][h2*2+1]));
            rm = fmaxf(rm, __shfl_xor_sync(0xffffffffu, rm, 1));
            rm = fmaxf(rm, __shfl_xor_sync(0xffffffffu, rm, 2));
            float nm = fmaxf(m[h2], rm);
            float alpha = __expf(m[h2] - nm);
            float rs = 0.f;
            #pragma unroll
            for (int nt = 0; nt < 8; nt++) {
                float p0 = __expf(sfr[nt][h2*2]   - nm);
                float p1 = __expf(sfr[nt][h2*2+1] - nm);
                sfr[nt][h2*2] = p0; sfr[nt][h2*2+1] = p1;
                rs += p0 + p1;
            }
            rs += __shfl_xor_sync(0xffffffffu, rs, 1);
            rs += __shfl_xor_sync(0xffffffffu, rs, 2);
            l[h2] = l[h2]*alpha + rs;
            m[h2] = nm;
            #pragma unroll
            for (int nt = 0; nt < 8; nt++) {
                oacc[nt][h2*2]   *= alpha;
                oacc[nt][h2*2+1] *= alpha;
            }
        }

        __syncthreads();     // all warps finished reading K from ps

        // ---- write P (tf32) into ps; each warp writes only its own 16 rows
        #pragma unroll
        for (int nt = 0; nt < 8; nt++) {
            #pragma unroll
            for (int h2 = 0; h2 < 2; h2++) {
                float* d = ps + (wrow + gid + h2*8)*ASTQ + nt*8 + 2*tig;
                d[0] = to_tf32(sfr[nt][h2*2]);
                d[1] = to_tf32(sfr[nt][h2*2+1]);
            }
        }
        __syncwarp();

        // ---- O += P @ V
        #pragma unroll
        for (int ks8 = 0; ks8 < 8; ks8++) {
            const int kb = ks8*8;
            uint32_t a[4];
            a[0] = __float_as_uint(ps[(wrow+gid  )*ASTQ + kb + tig    ]);
            a[1] = __float_as_uint(ps[(wrow+gid+8)*ASTQ + kb + tig    ]);
            a[2] = __float_as_uint(ps[(wrow+gid  )*ASTQ + kb + tig + 4]);
            a[3] = __float_as_uint(ps[(wrow+gid+8)*ASTQ + kb + tig + 4]);
            #pragma unroll
            for (int nt = 0; nt < 8; nt++) {
                uint32_t bf[2];
                bf[0] = __float_as_uint(vs[(kb+tig  )*ASTV + nt*8 + gid]);
                bf[1] = __float_as_uint(vs[(kb+tig+4)*ASTV + nt*8 + gid]);
                mma_tf32(oacc[nt], a, bf);
            }
        }
    }

    // ---- epilogue: O = acc / l
    float inv0 = 1.f / l[0];
    float inv1 = 1.f / l[1];
    size_t r0 = (size_t)(b*TLEN_ + qbase + wrow + gid)*ostride + h*DH_;
    size_t r1 = r0 + (size_t)8*ostride;
    #pragma unroll
    for (int nt = 0; nt < 8; nt++) {
        int col = nt*8 + 2*tig;
        *(float2*)&O[r0 + col] = make_float2(oacc[nt][0]*inv0, oacc[nt][1]*inv0);
        *(float2*)&O[r1 + col] = make_float2(oacc[nt][2]*inv1, oacc[nt][3]*inv1);
    }
}

// ---------------- host orchestration ----------------
extern "C" void kernel_launch(void* const* d_in, const int* in_sizes, int n_in,
                              void* d_out, int out_size)
{
    (void)in_sizes; (void)n_in; (void)out_size;
    const int*   tgt    = (const int*)  d_in[0];
    const int*   src    = (const int*)  d_in[1];
    const float* memory = (const float*)d_in[2];
    const float* emb    = (const float*)d_in[3];
    const float* sa_w   = (const float*)d_in[4];
    const float* sa_b   = (const float*)d_in[5];
    const float* ca_w   = (const float*)d_in[6];
    const float* ca_b   = (const float*)d_in[7];
    const float* ln_g   = (const float*)d_in[8];
    const float* ln_b   = (const float*)d_in[9];
    const float* ff_w1  = (const float*)d_in[10];
    const float* ff_b1  = (const float*)d_in[11];
    const float* ff_w2  = (const float*)d_in[12];
    const float* ff_b2  = (const float*)d_in[13];
    const float* out_g  = (const float*)d_in[14];
    const float* out_b  = (const float*)d_in[15];
    float* out = (float*)d_out;

    float *res, *res2, *lnb, *qkv, *kv, *ctx, *ff;
    cudaGetSymbolAddress((void**)&res,  g_res);
    cudaGetSymbolAddress((void**)&res2, g_res2);
    cudaGetSymbolAddress((void**)&lnb,  g_lnb);
    cudaGetSymbolAddress((void**)&qkv,  g_qkv);
    cudaGetSymbolAddress((void**)&kv,   g_kv);
    cudaGetSymbolAddress((void**)&ctx,  g_ctx);
    cudaGetSymbolAddress((void**)&ff,   g_ff);

    cudaFuncSetAttribute(attn_tc<true>,  cudaFuncAttributeMaxDynamicSharedMemorySize, ATTN_SMEM);
    cudaFuncSetAttribute(attn_tc<false>, cudaFuncAttributeMaxDynamicSharedMemorySize, ATTN_SMEM);

    embed_kernel<<<BT_, 256>>>(tgt, emb, res);

    const dim3 g768 (DMODEL/128, BT_/128);
    const dim3 g1536(2*DMODEL/128, BS_/128);
    const dim3 g2304(3*DMODEL/128, BT_/128);
    const dim3 g3072(DFF_/128, BT_/128);
    const dim3 attn_grid(TLEN_/64, NH, BB);

    for (int i = 0; i < NL; i++) {
        const float* saw = sa_w + (size_t)i*4*DMODEL*DMODEL;
        const float* sab = sa_b + (size_t)i*4*DMODEL;
        const float* caw = ca_w + (size_t)i*4*DMODEL*DMODEL;
        const float* cab = ca_b + (size_t)i*4*DMODEL;
        const float* lg  = ln_g + (size_t)i*3*DMODEL;
        const float* lb  = ln_b + (size_t)i*3*DMODEL;

        // ----- self attention -----
        ln_kernel<<<BT_, 256>>>(res, lg, lb, lnb);
        gemm_tc<true,false,false><<<g2304, 256>>>(lnb, saw, sab, nullptr, qkv,
                                                  BT_, 3*DMODEL, DMODEL);
        attn_tc<true><<<attn_grid, 128, ATTN_SMEM>>>(
            qkv, 3*DMODEL, qkv + DMODEL, 3*DMODEL, qkv + 2*DMODEL, 3*DMODEL,
            tgt, TLEN_, ctx, DMODEL);
        gemm_tc<true,true,false><<<g768, 256>>>(ctx, saw + (size_t)3*DMODEL*DMODEL,
                                                sab + 3*DMODEL, res, res2,
                                                BT_, DMODEL, DMODEL);

        // ----- cross attention -----
        ln_kernel<<<BT_, 256>>>(res2, lg + DMODEL, lb + DMODEL, lnb);
        gemm_tc<true,false,false><<<g768, 256>>>(lnb, caw, cab, nullptr, qkv,
                                                 BT_, DMODEL, DMODEL);
        gemm_tc<true,false,false><<<g1536, 256>>>(memory, caw + (size_t)DMODEL*DMODEL,
                                                  cab + DMODEL, nullptr, kv,
                                                  BS_, 2*DMODEL, DMODEL);
        attn_tc<false><<<attn_grid, 128, ATTN_SMEM>>>(
            qkv, DMODEL, kv, 2*DMODEL, kv + DMODEL, 2*DMODEL,
            src, SLEN_, ctx, DMODEL);
        gemm_tc<true,true,false><<<g768, 256>>>(ctx, caw + (size_t)3*DMODEL*DMODEL,
                                                cab + 3*DMODEL, res2, res,
                                                BT_, DMODEL, DMODEL);

        // ----- FFN -----
        ln_kernel<<<BT_, 256>>>(res, lg + 2*DMODEL, lb + 2*DMODEL, lnb);
        gemm_tc<true,false,true><<<g3072, 256>>>(lnb, ff_w1 + (size_t)i*DFF_*DMODEL,
                                                 ff_b1 + (size_t)i*DFF_, nullptr, ff,
                                                 BT_, DFF_, DMODEL);
        gemm_tc<true,true,false><<<g768, 256>>>(ff, ff_w2 + (size_t)i*DMODEL*DFF_,
                                                ff_b2 + (size_t)i*DMODEL, res, res2,
                                                BT_, DMODEL, DFF_);

        float* tmp = res; res = res2; res2 = tmp;
    }

    ln_kernel<<<BT_, 256>>>(res, out_g, out_b, out);
}

// round 4
// speedup vs baseline: 2.3598x; 1.0622x over previous
#include <cuda_runtime.h>
#include <math.h>
#include <stdint.h>

// ---------------- problem constants ----------------
#define NL    6
#define DMODEL 768
#define NH    12
#define DFF_  3072
#define BB    8
#define TLEN_ 512
#define SLEN_ 512
#define DH_   64
#define BT_   (BB*TLEN_)   // 4096 target tokens
#define BS_   (BB*SLEN_)   // 4096 source tokens

// ---------------- scratch (device globals: allocation-free) ----------------
__device__ float g_res [BT_*DMODEL];
__device__ float g_res2[BT_*DMODEL];
__device__ float g_lnb [BT_*DMODEL];
__device__ float g_qkv [BT_*3*DMODEL];
__device__ float g_kv  [BS_*2*DMODEL];
__device__ float g_ctx [BT_*DMODEL];
__device__ float g_ff  [BT_*DFF_];
// tf32 pre-rounded weights / memory
__device__ float g_wsa[(size_t)NL*4*DMODEL*DMODEL];
__device__ float g_wca[(size_t)NL*4*DMODEL*DMODEL];
__device__ float g_w1 [(size_t)NL*DFF_*DMODEL];
__device__ float g_w2 [(size_t)NL*DMODEL*DFF_];
__device__ float g_mem[(size_t)BS_*DMODEL];

// ---------------- TF32 helpers ----------------
__device__ __forceinline__ float to_tf32(float x)
{
    float r;
    asm("cvt.rna.tf32.f32 %0, %1;" : "=f"(r) : "f"(x));
    return r;
}

__device__ __forceinline__ void mma_tf32(float c[4], const uint32_t a[4], const uint32_t b[2])
{
    asm volatile(
        "mma.sync.aligned.m16n8k8.row.col.f32.tf32.tf32.f32 "
        "{%0,%1,%2,%3}, {%4,%5,%6,%7}, {%8,%9}, {%0,%1,%2,%3};"
        : "+f"(c[0]), "+f"(c[1]), "+f"(c[2]), "+f"(c[3])
        : "r"(a[0]), "r"(a[1]), "r"(a[2]), "r"(a[3]), "r"(b[0]), "r"(b[1]));
}

__device__ __forceinline__ void cp16(float* dst, const float* src)
{
    uint32_t s = (uint32_t)__cvta_generic_to_shared(dst);
    asm volatile("cp.async.cg.shared.global [%0], [%1], 16;" :: "r"(s), "l"(src));
}

// ---------------- pre-round kernel (fp32 -> tf32-rounded fp32) ----------------
__global__ void round_tf32_kernel(const float4* __restrict__ in,
                                  float4* __restrict__ out, int n4)
{
    int i = blockIdx.x * 256 + threadIdx.x;
    if (i < n4) {
        float4 v = in[i];
        v.x = to_tf32(v.x); v.y = to_tf32(v.y);
        v.z = to_tf32(v.z); v.w = to_tf32(v.w);
        out[i] = v;
    }
}

// ---------------- embedding + positional encoding ----------------
__global__ void embed_kernel(const int* __restrict__ tgt,
                             const float* __restrict__ emb,
                             float* __restrict__ out)
{
    int row = blockIdx.x;              // b*T + t
    int t   = row & (TLEN_ - 1);
    int tok = tgt[row];
    const float* e = emb + (size_t)tok * DMODEL;
    const float c = (float)(-9.210340371976184 / (double)DMODEL);  // -ln(10000)/D
    for (int d = threadIdx.x; d < DMODEL; d += blockDim.x) {
        int k2 = d & ~1;                              // 2*i
        float div = expf((float)k2 * c);
        float ang = (float)t * div;
        float pe  = (d & 1) ? cosf(ang) : sinf(ang);
        out[(size_t)row*DMODEL + d] = e[d] * 27.712812921102035f + pe; // sqrt(768)
    }
}

// ---------------- layernorm ----------------
__device__ __forceinline__ float blockReduceSum(float v)
{
    __shared__ float sh[9];
    int lane = threadIdx.x & 31, w = threadIdx.x >> 5;
    #pragma unroll
    for (int o = 16; o; o >>= 1) v += __shfl_xor_sync(0xffffffffu, v, o);
    __syncthreads();
    if (lane == 0) sh[w] = v;
    __syncthreads();
    if (threadIdx.x == 0) {
        float t = 0.f;
        #pragma unroll
        for (int i = 0; i < 8; i++) t += sh[i];
        sh[8] = t;
    }
    __syncthreads();
    return sh[8];
}

template<bool ROUND>
__global__ __launch_bounds__(256) void ln_kernel(const float* __restrict__ X,
                                                 const float* __restrict__ gam,
                                                 const float* __restrict__ bet,
                                                 float* __restrict__ Y)
{
    int row = blockIdx.x;
    const float* x = X + (size_t)row * DMODEL;
    float s = 0.f;
    for (int d = threadIdx.x; d < DMODEL; d += 256) s += x[d];
    s = blockReduceSum(s);
    float mean = s / (float)DMODEL;
    float v = 0.f;
    for (int d = threadIdx.x; d < DMODEL; d += 256) { float t = x[d] - mean; v += t * t; }
    v = blockReduceSum(v);
    float inv = rsqrtf(v / (float)DMODEL + 1e-6f);
    for (int d = threadIdx.x; d < DMODEL; d += 256) {
        float y = (x[d] - mean) * inv * gam[d] + bet[d];
        Y[(size_t)row*DMODEL + d] = ROUND ? to_tf32(y) : y;
    }
}

// ---------------- TF32 tensor-core GEMM (cp.async double-buffered) ----------------
// C[M,N] = A[M,K] @ W[N,K]^T (+bias)(+gelu)(+round)(+resid)
// 128x128 block tile, BK=32, 256 threads = 8 warps, warp tile 32x64.
// Inputs must be pre-rounded to tf32 (mma truncation is then exact).

#define GST 36   // smem row stride (floats): bank = (4*gid+tig)%32, conflict-free
#define GEMM_SMEM (4*128*GST*4)   // 2 bufs x (As + Bs)

template<bool BIAS, bool RESID, bool GELU, bool ROUND>
__global__ __launch_bounds__(256, 2) void gemm_tc(
    const float* __restrict__ A, const float* __restrict__ W,
    const float* __restrict__ bias, const float* __restrict__ Rm,
    float* __restrict__ C, int M, int N, int K)
{
    extern __shared__ float sh[];
    float* AsB = sh;                  // [2][128][GST]
    float* BsB = sh + 2*128*GST;      // [2][128][GST]

    const int tid  = threadIdx.x;
    const int warp = tid >> 5, lane = tid & 31;
    const int gid  = lane >> 2, tig = lane & 3;
    const int brow = blockIdx.y * 128, bcol = blockIdx.x * 128;
    const int wr   = (warp >> 1) * 32;   // warp row offset (0,32,64,96)
    const int wc   = (warp & 1) * 64;    // warp col offset (0,64)

    const int grow = tid >> 1;           // 0..127
    const int gk   = (tid & 1) * 16;     // 0 or 16
    const float* Ap = A + (size_t)(brow + grow) * K + gk;
    const float* Wp = W + (size_t)(bcol + grow) * K + gk;

    float acc[2][8][4];
    #pragma unroll
    for (int mt = 0; mt < 2; mt++)
        #pragma unroll
        for (int nt = 0; nt < 8; nt++)
            #pragma unroll
            for (int r = 0; r < 4; r++) acc[mt][nt][r] = 0.f;

    const int niter = K >> 5;

    // prologue: stage iter 0 into buf 0
    {
        float* as = AsB + grow*GST + gk;
        float* bs = BsB + grow*GST + gk;
        #pragma unroll
        for (int j = 0; j < 4; j++) {
            cp16(as + j*4, Ap + j*4);
            cp16(bs + j*4, Wp + j*4);
        }
        asm volatile("cp.async.commit_group;");
    }

    for (int it = 0; it < niter; it++) {
        const int buf = it & 1;
        if (it + 1 < niter) {
            const int nb = buf ^ 1;
            const float* a = Ap + (it+1)*32;
            const float* w = Wp + (it+1)*32;
            float* as = AsB + nb*128*GST + grow*GST + gk;
            float* bs = BsB + nb*128*GST + grow*GST + gk;
            #pragma unroll
            for (int j = 0; j < 4; j++) {
                cp16(as + j*4, a + j*4);
                cp16(bs + j*4, w + j*4);
            }
            asm volatile("cp.async.commit_group;");
            asm volatile("cp.async.wait_group 1;");
        } else {
            asm volatile("cp.async.wait_group 0;");
        }
        __syncthreads();

        const float* as = AsB + buf*128*GST;
        const float* bs = BsB + buf*128*GST;
        #pragma unroll
        for (int ks = 0; ks < 4; ks++) {
            const int kb = ks * 8;
            uint32_t afr[2][4];
            #pragma unroll
            for (int mt = 0; mt < 2; mt++) {
                int r0 = wr + mt*16 + gid;
                afr[mt][0] = __float_as_uint(as[(r0    )*GST + kb + tig    ]);
                afr[mt][1] = __float_as_uint(as[(r0 + 8)*GST + kb + tig    ]);
                afr[mt][2] = __float_as_uint(as[(r0    )*GST + kb + tig + 4]);
                afr[mt][3] = __float_as_uint(as[(r0 + 8)*GST + kb + tig + 4]);
            }
            #pragma unroll
            for (int nt = 0; nt < 8; nt++) {
                int c0 = wc + nt*8 + gid;
                uint32_t bfr[2];
                bfr[0] = __float_as_uint(bs[c0*GST + kb + tig    ]);
                bfr[1] = __float_as_uint(bs[c0*GST + kb + tig + 4]);
                mma_tf32(acc[0][nt], afr[0], bfr);
                mma_tf32(acc[1][nt], afr[1], bfr);
            }
        }
        __syncthreads();   // all warps done reading buf before it is overwritten
    }

    #pragma unroll
    for (int mt = 0; mt < 2; mt++) {
        #pragma unroll
        for (int half = 0; half < 2; half++) {
            int row = brow + wr + mt*16 + gid + half*8;
            #pragma unroll
            for (int nt = 0; nt < 8; nt++) {
                int col = bcol + wc + nt*8 + 2*tig;
                float v0 = acc[mt][nt][half*2 + 0];
                float v1 = acc[mt][nt][half*2 + 1];
                if (BIAS) { v0 += bias[col]; v1 += bias[col+1]; }
                if (GELU) {
                    float u0 = v0, u1 = v1;
                    v0 = 0.5f*u0*(1.f + tanhf(0.7978845608028654f*(u0 + 0.044715f*u0*u0*u0)));
                    v1 = 0.5f*u1*(1.f + tanhf(0.7978845608028654f*(u1 + 0.044715f*u1*u1*u1)));
                }
                if (ROUND) { v0 = to_tf32(v0); v1 = to_tf32(v1); }
                if (RESID) {
                    v0 += Rm[(size_t)row*N + col];
                    v1 += Rm[(size_t)row*N + col + 1];
                }
                *(float2*)&C[(size_t)row*N + col] = make_float2(v0, v1);
            }
        }
    }
}

// ---------------- tensor-core flash attention (TF32 mma) ----------------
// 128 threads = 4 warps. q tile 64 rows (16 per warp), k tile 64, DH=64.
#define ASTQ 68
#define ASTV 72
#define ATTN_SMEM ((2*64*ASTQ + 64*ASTV)*4)

template<bool CAUSAL>
__global__ __launch_bounds__(128) void attn_tc(
    const float* __restrict__ Q, int qstride,
    const float* __restrict__ Kp, int kstride,
    const float* __restrict__ Vp, int vstride,
    const int*  __restrict__ tok, int klen,
    float* __restrict__ O, int ostride)
{
    extern __shared__ float sm[];
    float* qs = sm;                    // [64][ASTQ]
    float* ps = sm + 64*ASTQ;          // [64][ASTQ]   K tile, reused for P
    float* vs = sm + 2*64*ASTQ;        // [64][ASTV]
    __shared__ int smask[64];

    const int tid  = threadIdx.x;
    const int warp = tid >> 5, lane = tid & 31;
    const int gid  = lane >> 2, tig = lane & 3;
    const int wrow = warp * 16;
    const int qt = blockIdx.x, h = blockIdx.y, b = blockIdx.z;
    const int qbase = qt * 64;

    // load Q tile (scaled, tf32)
    {
        int lr = tid >> 1;
        int lc = (tid & 1) * 32;
        const float* qp = Q + (size_t)(b*TLEN_ + qbase + lr)*qstride + h*DH_ + lc;
        #pragma unroll
        for (int j = 0; j < 8; j++) {
            float4 v = *(const float4*)(qp + j*4);
            float* d = qs + lr*ASTQ + lc + j*4;
            d[0] = to_tf32(v.x*0.125f); d[1] = to_tf32(v.y*0.125f);
            d[2] = to_tf32(v.z*0.125f); d[3] = to_tf32(v.w*0.125f);
        }
    }

    float m[2] = {-INFINITY, -INFINITY};
    float l[2] = {0.f, 0.f};
    float oacc[8][4];
    #pragma unroll
    for (int nt = 0; nt < 8; nt++)
        #pragma unroll
        for (int r = 0; r < 4; r++) oacc[nt][r] = 0.f;

    const int nkt = CAUSAL ? (qt + 1) : (klen >> 6);
    for (int kt = 0; kt < nkt; kt++) {
        __syncthreads();
        {
            int lr = tid >> 1;
            int lc = (tid & 1) * 32;
            const float* kp = Kp + (size_t)(b*klen + kt*64 + lr)*kstride + h*DH_ + lc;
            const float* vp = Vp + (size_t)(b*klen + kt*64 + lr)*vstride + h*DH_ + lc;
            #pragma unroll
            for (int j = 0; j < 8; j++) {
                float4 kv4 = *(const float4*)(kp + j*4);
                float* dk = ps + lr*ASTQ + lc + j*4;
                dk[0] = to_tf32(kv4.x); dk[1] = to_tf32(kv4.y);
                dk[2] = to_tf32(kv4.z); dk[3] = to_tf32(kv4.w);
                float4 vv4 = *(const float4*)(vp + j*4);
                float* dv = vs + lr*ASTV + lc + j*4;
                dv[0] = to_tf32(vv4.x); dv[1] = to_tf32(vv4.y);
                dv[2] = to_tf32(vv4.z); dv[3] = to_tf32(vv4.w);
            }
            if (tid < 64) smask[tid] = (tok[b*klen + kt*64 + tid] == 0);
        }
        __syncthreads();

        // ---- S = Q @ K^T
        float sfr[8][4];
        #pragma unroll
        for (int nt = 0; nt < 8; nt++)
            #pragma unroll
            for (int r = 0; r < 4; r++) sfr[nt][r] = 0.f;

        #pragma unroll
        for (int ks8 = 0; ks8 < 8; ks8++) {
            const int kb = ks8*8;
            uint32_t a[4];
            a[0] = __float_as_uint(qs[(wrow+gid  )*ASTQ + kb + tig    ]);
            a[1] = __float_as_uint(qs[(wrow+gid+8)*ASTQ + kb + tig    ]);
            a[2] = __float_as_uint(qs[(wrow+gid  )*ASTQ + kb + tig + 4]);
            a[3] = __float_as_uint(qs[(wrow+gid+8)*ASTQ + kb + tig + 4]);
            #pragma unroll
            for (int nt = 0; nt < 8; nt++) {
                uint32_t bf[2];
                bf[0] = __float_as_uint(ps[(nt*8+gid)*ASTQ + kb + tig    ]);
                bf[1] = __float_as_uint(ps[(nt*8+gid)*ASTQ + kb + tig + 4]);
                mma_tf32(sfr[nt], a, bf);
            }
        }

        // ---- mask (replace with -1e18, matching reference)
        #pragma unroll
        for (int nt = 0; nt < 8; nt++) {
            #pragma unroll
            for (int e = 0; e < 4; e++) {
                int cl = nt*8 + 2*tig + (e & 1);
                int rowg = qbase + wrow + gid + (e >> 1)*8;
                int colg = kt*64 + cl;
                bool msk = (smask[cl] != 0) || (CAUSAL && colg > rowg);
                if (msk) sfr[nt][e] = -1e18f;
            }
        }

        // ---- online softmax
        #pragma unroll
        for (int h2 = 0; h2 < 2; h2++) {
            float rm = -INFINITY;
            #pragma unroll
            for (int nt = 0; nt < 8; nt++)
                rm = fmaxf(rm, fmaxf(sfr[nt][h2*2], sfr[nt][h2*2+1]));
            rm = fmaxf(rm, __shfl_xor_sync(0xffffffffu, rm, 1));
            rm = fmaxf(rm, __shfl_xor_sync(0xffffffffu, rm, 2));
            float nm = fmaxf(m[h2], rm);
            float alpha = __expf(m[h2] - nm);
            float rs = 0.f;
            #pragma unroll
            for (int nt = 0; nt < 8; nt++) {
                float p0 = __expf(sfr[nt][h2*2]   - nm);
                float p1 = __expf(sfr[nt][h2*2+1] - nm);
                sfr[nt][h2*2] = p0; sfr[nt][h2*2+1] = p1;
                rs += p0 + p1;
            }
            rs += __shfl_xor_sync(0xffffffffu, rs, 1);
            rs += __shfl_xor_sync(0xffffffffu, rs, 2);
            l[h2] = l[h2]*alpha + rs;
            m[h2] = nm;
            #pragma unroll
            for (int nt = 0; nt < 8; nt++) {
                oacc[nt][h2*2]   *= alpha;
                oacc[nt][h2*2+1] *= alpha;
            }
        }

        __syncthreads();

        // ---- write P (tf32) into ps
        #pragma unroll
        for (int nt = 0; nt < 8; nt++) {
            #pragma unroll
            for (int h2 = 0; h2 < 2; h2++) {
                float* d = ps + (wrow + gid + h2*8)*ASTQ + nt*8 + 2*tig;
                d[0] = to_tf32(sfr[nt][h2*2]);
                d[1] = to_tf32(sfr[nt][h2*2+1]);
            }
        }
        __syncwarp();

        // ---- O += P @ V
        #pragma unroll
        for (int ks8 = 0; ks8 < 8; ks8++) {
            const int kb = ks8*8;
            uint32_t a[4];
            a[0] = __float_as_uint(ps[(wrow+gid  )*ASTQ + kb + tig    ]);
            a[1] = __float_as_uint(ps[(wrow+gid+8)*ASTQ + kb + tig    ]);
            a[2] = __float_as_uint(ps[(wrow+gid  )*ASTQ + kb + tig + 4]);
            a[3] = __float_as_uint(ps[(wrow+gid+8)*ASTQ + kb + tig + 4]);
            #pragma unroll
            for (int nt = 0; nt < 8; nt++) {
                uint32_t bf[2];
                bf[0] = __float_as_uint(vs[(kb+tig  )*ASTV + nt*8 + gid]);
                bf[1] = __float_as_uint(vs[(kb+tig+4)*ASTV + nt*8 + gid]);
                mma_tf32(oacc[nt], a, bf);
            }
        }
    }

    // ---- epilogue: O = tf32(acc / l)  (ctx feeds GEMM A-input)
    float inv0 = 1.f / l[0];
    float inv1 = 1.f / l[1];
    size_t r0 = (size_t)(b*TLEN_ + qbase + wrow + gid)*ostride + h*DH_;
    size_t r1 = r0 + (size_t)8*ostride;
    #pragma unroll
    for (int nt = 0; nt < 8; nt++) {
        int col = nt*8 + 2*tig;
        *(float2*)&O[r0 + col] = make_float2(to_tf32(oacc[nt][0]*inv0), to_tf32(oacc[nt][1]*inv0));
        *(float2*)&O[r1 + col] = make_float2(to_tf32(oacc[nt][2]*inv1), to_tf32(oacc[nt][3]*inv1));
    }
}

// ---------------- host orchestration ----------------
extern "C" void kernel_launch(void* const* d_in, const int* in_sizes, int n_in,
                              void* d_out, int out_size)
{
    (void)in_sizes; (void)n_in; (void)out_size;
    const int*   tgt    = (const int*)  d_in[0];
    const int*   src    = (const int*)  d_in[1];
    const float* memory = (const float*)d_in[2];
    const float* emb    = (const float*)d_in[3];
    const float* sa_w   = (const float*)d_in[4];
    const float* sa_b   = (const float*)d_in[5];
    const float* ca_w   = (const float*)d_in[6];
    const float* ca_b   = (const float*)d_in[7];
    const float* ln_g   = (const float*)d_in[8];
    const float* ln_b   = (const float*)d_in[9];
    const float* ff_w1  = (const float*)d_in[10];
    const float* ff_b1  = (const float*)d_in[11];
    const float* ff_w2  = (const float*)d_in[12];
    const float* ff_b2  = (const float*)d_in[13];
    const float* out_g  = (const float*)d_in[14];
    const float* out_b  = (const float*)d_in[15];
    float* out = (float*)d_out;

    float *res, *res2, *lnb, *qkv, *kv, *ctx, *ff;
    float *wsa, *wca, *w1, *w2, *mem;
    cudaGetSymbolAddress((void**)&res,  g_res);
    cudaGetSymbolAddress((void**)&res2, g_res2);
    cudaGetSymbolAddress((void**)&lnb,  g_lnb);
    cudaGetSymbolAddress((void**)&qkv,  g_qkv);
    cudaGetSymbolAddress((void**)&kv,   g_kv);
    cudaGetSymbolAddress((void**)&ctx,  g_ctx);
    cudaGetSymbolAddress((void**)&ff,   g_ff);
    cudaGetSymbolAddress((void**)&wsa,  g_wsa);
    cudaGetSymbolAddress((void**)&wca,  g_wca);
    cudaGetSymbolAddress((void**)&w1,   g_w1);
    cudaGetSymbolAddress((void**)&w2,   g_w2);
    cudaGetSymbolAddress((void**)&mem,  g_mem);

    cudaFuncSetAttribute(attn_tc<true>,  cudaFuncAttributeMaxDynamicSharedMemorySize, ATTN_SMEM);
    cudaFuncSetAttribute(attn_tc<false>, cudaFuncAttributeMaxDynamicSharedMemorySize, ATTN_SMEM);
    cudaFuncSetAttribute((gemm_tc<true,false,false,false>), cudaFuncAttributeMaxDynamicSharedMemorySize, GEMM_SMEM);
    cudaFuncSetAttribute((gemm_tc<true,true ,false,false>), cudaFuncAttributeMaxDynamicSharedMemorySize, GEMM_SMEM);
    cudaFuncSetAttribute((gemm_tc<true,false,true ,true >), cudaFuncAttributeMaxDynamicSharedMemorySize, GEMM_SMEM);

    // pre-round weights + memory to tf32 (once per launch, ~75us)
    {
        const int WN4 = NL*4*DMODEL*DMODEL/4;
        round_tf32_kernel<<<(WN4+255)/256, 256>>>((const float4*)sa_w, (float4*)wsa, WN4);
        round_tf32_kernel<<<(WN4+255)/256, 256>>>((const float4*)ca_w, (float4*)wca, WN4);
        const int F1N4 = NL*DFF_*DMODEL/4;
        round_tf32_kernel<<<(F1N4+255)/256, 256>>>((const float4*)ff_w1, (float4*)w1, F1N4);
        round_tf32_kernel<<<(F1N4+255)/256, 256>>>((const float4*)ff_w2, (float4*)w2, F1N4);
        const int MN4 = BS_*DMODEL/4;
        round_tf32_kernel<<<(MN4+255)/256, 256>>>((const float4*)memory, (float4*)mem, MN4);
    }

    embed_kernel<<<BT_, 256>>>(tgt, emb, res);

    const dim3 g768 (DMODEL/128, BT_/128);
    const dim3 g1536(2*DMODEL/128, BS_/128);
    const dim3 g2304(3*DMODEL/128, BT_/128);
    const dim3 g3072(DFF_/128, BT_/128);
    const dim3 attn_grid(TLEN_/64, NH, BB);

    for (int i = 0; i < NL; i++) {
        const float* saw = wsa + (size_t)i*4*DMODEL*DMODEL;
        const float* sab = sa_b + (size_t)i*4*DMODEL;
        const float* caw = wca + (size_t)i*4*DMODEL*DMODEL;
        const float* cab = ca_b + (size_t)i*4*DMODEL;
        const float* lg  = ln_g + (size_t)i*3*DMODEL;
        const float* lb  = ln_b + (size_t)i*3*DMODEL;

        // ----- self attention -----
        ln_kernel<true><<<BT_, 256>>>(res, lg, lb, lnb);
        gemm_tc<true,false,false,false><<<g2304, 256, GEMM_SMEM>>>(lnb, saw, sab, nullptr, qkv,
                                                  BT_, 3*DMODEL, DMODEL);
        attn_tc<true><<<attn_grid, 128, ATTN_SMEM>>>(
            qkv, 3*DMODEL, qkv + DMODEL, 3*DMODEL, qkv + 2*DMODEL, 3*DMODEL,
            tgt, TLEN_, ctx, DMODEL);
        gemm_tc<true,true,false,false><<<g768, 256, GEMM_SMEM>>>(ctx, saw + (size_t)3*DMODEL*DMODEL,
                                                sab + 3*DMODEL, res, res2,
                                                BT_, DMODEL, DMODEL);

        // ----- cross attention -----
        ln_kernel<true><<<BT_, 256>>>(res2, lg + DMODEL, lb + DMODEL, lnb);
        gemm_tc<true,false,false,false><<<g768, 256, GEMM_SMEM>>>(lnb, caw, cab, nullptr, qkv,
                                                 BT_, DMODEL, DMODEL);
        gemm_tc<true,false,false,false><<<g1536, 256, GEMM_SMEM>>>(mem, caw + (size_t)DMODEL*DMODEL,
                                                  cab + DMODEL, nullptr, kv,
                                                  BS_, 2*DMODEL, DMODEL);
        attn_tc<false><<<attn_grid, 128, ATTN_SMEM>>>(
            qkv, DMODEL, kv, 2*DMODEL, kv + DMODEL, 2*DMODEL,
            src, SLEN_, ctx, DMODEL);
        gemm_tc<true,true,false,false><<<g768, 256, GEMM_SMEM>>>(ctx, caw + (size_t)3*DMODEL*DMODEL,
                                                cab + 3*DMODEL, res2, res,
                                                BT_, DMODEL, DMODEL);

        // ----- FFN -----
        ln_kernel<true><<<BT_, 256>>>(res, lg + 2*DMODEL, lb + 2*DMODEL, lnb);
        gemm_tc<true,false,true,true><<<g3072, 256, GEMM_SMEM>>>(lnb, w1 + (size_t)i*DFF_*DMODEL,
                                                 ff_b1 + (size_t)i*DFF_, nullptr, ff,
                                                 BT_, DFF_, DMODEL);
        gemm_tc<true,true,false,false><<<g768, 256, GEMM_SMEM>>>(ff, w2 + (size_t)i*DMODEL*DFF_,
                                                ff_b2 + (size_t)i*DMODEL, res, res2,
                                                BT_, DMODEL, DFF_);

        float* tmp = res; res = res2; res2 = tmp;
    }

    ln_kernel<false><<<BT_, 256>>>(res, out_g, out_b, out);
}